// round 2
// baseline (speedup 1.0000x reference)
#include <cuda_runtime.h>
#include <cuda_bf16.h>
#include <cstdint>

// Problem constants
#define B_  16
#define K_  29
#define KP  32           // K padded to 32 (pad rows hold 0)
#define C_  512
#define S_  16384        // 128*128
#define SPLIT 16         // s-split for kernel 2
#define CHUNK (S_ / SPLIT)   // 1024 s per block
#define TILE 128             // s staged per shared tile

// Scratch: normalized attention, padded: [B][KP][S]  (32 MB), same layout as probs
__device__ float g_attn[(size_t)B_ * KP * S_];
// Per (b,k): {row max, 1/sum}
__device__ float2 g_stats[B_ * KP];

// ---------------- packed f32x2 helpers ----------------
__device__ __forceinline__ void fma2(unsigned long long& acc,
                                     unsigned long long a,
                                     unsigned long long b) {
    asm("fma.rn.f32x2 %0, %1, %2, %0;" : "+l"(acc) : "l"(a), "l"(b));
}
__device__ __forceinline__ void unpack2(unsigned long long d, float& lo, float& hi) {
    asm("mov.b64 {%0, %1}, %2;" : "=f"(lo), "=f"(hi) : "l"(d));
}

// ---------------- kernel 0: zero the output ----------------
__global__ void k0_zero(float* __restrict__ out, int n) {
    int i = blockIdx.x * blockDim.x + threadIdx.x;
    if (i < n) out[i] = 0.0f;
}

// ---------------- kernel 1a: per-row max and 1/sum(exp) ----------------
__global__ __launch_bounds__(256) void k1a_stats(const float* __restrict__ probs) {
    const int k = blockIdx.x;   // 0..28
    const int b = blockIdx.y;   // 0..15
    const int tid = threadIdx.x;
    const float* row = probs + ((size_t)(b * K_ + k)) * S_;

    __shared__ float red[256];

    float m = -1e30f;
    for (int i = tid; i < S_; i += 256) m = fmaxf(m, row[i]);
    red[tid] = m;
    __syncthreads();
    for (int off = 128; off > 0; off >>= 1) {
        if (tid < off) red[tid] = fmaxf(red[tid], red[tid + off]);
        __syncthreads();
    }
    m = red[0];
    __syncthreads();

    float s = 0.0f;
    for (int i = tid; i < S_; i += 256) s += __expf(row[i] - m);
    red[tid] = s;
    __syncthreads();
    for (int off = 128; off > 0; off >>= 1) {
        if (tid < off) red[tid] += red[tid + off];
        __syncthreads();
    }
    if (tid == 0) g_stats[b * KP + k] = make_float2(m, 1.0f / red[0]);
}

// ---------------- kernel 1b: normalized attn in [b][kp][s] layout ----------------
__global__ __launch_bounds__(256) void k1b_attn(const float* __restrict__ probs) {
    const int b = blockIdx.y;
    const int s = blockIdx.x * 256 + threadIdx.x;   // grid.x = 64

    __shared__ float sm[K_], si[K_];
    if (threadIdx.x < K_) {
        float2 st = g_stats[b * KP + threadIdx.x];
        sm[threadIdx.x] = st.x;
        si[threadIdx.x] = st.y;
    }
    __syncthreads();

    float* dst = g_attn + (size_t)b * KP * S_;
#pragma unroll
    for (int k = 0; k < K_; k++) {
        float x = probs[((size_t)(b * K_ + k)) * S_ + s];
        dst[(size_t)k * S_ + s] = __expf(x - sm[k]) * si[k];
    }
    // pad rows 29..31 = 0
    dst[(size_t)29 * S_ + s] = 0.0f;
    dst[(size_t)30 * S_ + s] = 0.0f;
    dst[(size_t)31 * S_ + s] = 0.0f;
}

// ---------------- kernel 2: out[b,c,k] = sum_s attn[b,k,s] * feats[b,c,s] ----------------
// grid: (SPLIT, C_/128, B_), block 128 = 4 warps.
// Warp w owns k in [8w, 8w+8). Lane l owns c = cbase + l + {0,32,64,96}.
// FFMA2 lanes pack (s even, s odd) partial sums; summed in the epilogue.
__global__ __launch_bounds__(128) void k2_gemm(const float* __restrict__ feats,
                                               float* __restrict__ out) {
    const int b    = blockIdx.z;
    const int warp = threadIdx.x >> 5;
    const int lane = threadIdx.x & 31;
    const int k0   = warp * 8;
    const int cb   = blockIdx.y * 128;
    const int s0   = blockIdx.x * CHUNK;

    const float* frow  = feats + ((size_t)(b * C_ + cb + lane)) * S_ + s0;
    const float* abase = g_attn + ((size_t)b * KP) * S_ + s0;

    __shared__ __align__(16) float sh[KP][TILE];   // 16 KB: [32 k][128 s]

    unsigned long long acc[4][8];
#pragma unroll
    for (int cc = 0; cc < 4; cc++)
#pragma unroll
        for (int kk = 0; kk < 8; kk++) acc[cc][kk] = 0ull;

    for (int t = 0; t < CHUNK; t += TILE) {
        __syncthreads();
        // stage attn tile [32 k][128 s] = 1024 float4 slots, coalesced per row
#pragma unroll
        for (int j = 0; j < 8; j++) {
            int idx = threadIdx.x + j * 128;
            int kk  = idx >> 5;        // 0..31
            int sc  = idx & 31;        // float4 column
            *(float4*)&sh[kk][sc * 4] =
                *(const float4*)(abase + (size_t)kk * S_ + t + sc * 4);
        }
        __syncthreads();

#pragma unroll 2
        for (int j = 0; j < TILE; j += 4) {
            // feats: 4 c rows, 4 s each -> two f32x2 pairs per row, no packing movs
            ulonglong2 fu[4];
#pragma unroll
            for (int cc = 0; cc < 4; cc++)
                fu[cc] = *(const ulonglong2*)(frow + (size_t)(cc * 32) * S_ + t + j);

#pragma unroll
            for (int kk = 0; kk < 8; kk++) {
                ulonglong2 a4 = *(const ulonglong2*)&sh[k0 + kk][j]; // LDS.128 broadcast
#pragma unroll
                for (int cc = 0; cc < 4; cc++) {
                    fma2(acc[cc][kk], a4.x, fu[cc].x);   // (s0,s1)
                    fma2(acc[cc][kk], a4.y, fu[cc].y);   // (s2,s3)
                }
            }
        }
    }

    // epilogue: out layout (B, C, K, 1) -> (b*C + c)*K + k ; skip pad k >= 29
#pragma unroll
    for (int cc = 0; cc < 4; cc++) {
        const int c = cb + lane + cc * 32;
        float* o = out + ((size_t)(b * C_ + c)) * K_;
#pragma unroll
        for (int kk = 0; kk < 8; kk++) {
            const int k = k0 + kk;
            if (k < K_) {
                float lo, hi;
                unpack2(acc[cc][kk], lo, hi);
                atomicAdd(o + k, lo + hi);
            }
        }
    }
}

extern "C" void kernel_launch(void* const* d_in, const int* in_sizes, int n_in,
                              void* d_out, int out_size) {
    const float* feats = (const float*)d_in[0];  // (16, 512, 128, 128)
    const float* probs = (const float*)d_in[1];  // (16, 29, 128, 128)
    float* out = (float*)d_out;                  // (16, 512, 29, 1) fp32

    k0_zero<<<(out_size + 1023) / 1024, 1024>>>(out, out_size);
    k1a_stats<<<dim3(K_, B_), 256>>>(probs);
    k1b_attn<<<dim3(S_ / 256, B_), 256>>>(probs);
    k2_gemm<<<dim3(SPLIT, C_ / 128, B_), 128>>>(feats, out);
}

// round 3
// speedup vs baseline: 2.0049x; 2.0049x over previous
#include <cuda_runtime.h>
#include <cuda_bf16.h>
#include <cstdint>

#define B_  16
#define K_  29
#define KP  32
#define C_  512
#define S_  16384
#define SPLIT 32
#define CHUNK (S_ / SPLIT)     // 512 s per block
#define STILE 32               // s per shared tile
#define NT (CHUNK / STILE)     // 16 tiles
#define FSTRIDE 36             // padded row stride (floats), 16B-aligned
#define FBUF (128 * FSTRIDE)   // 4608 floats per feats buffer
#define ABUF (KP * FSTRIDE)    // 1152 floats per attn buffer

// Normalized attention, padded: [B][KP][S] (32 MB)
__device__ float g_attn[(size_t)B_ * KP * S_];
__device__ float2 g_stats[B_ * KP];

__device__ __forceinline__ void fma2(unsigned long long& acc,
                                     unsigned long long a,
                                     unsigned long long b) {
    asm("fma.rn.f32x2 %0, %1, %2, %0;" : "+l"(acc) : "l"(a), "l"(b));
}
__device__ __forceinline__ void unpack2(unsigned long long d, float& lo, float& hi) {
    asm("mov.b64 {%0, %1}, %2;" : "=f"(lo), "=f"(hi) : "l"(d));
}
__device__ __forceinline__ uint32_t s2u(const void* p) {
    return (uint32_t)__cvta_generic_to_shared(p);
}
__device__ __forceinline__ void cp16(uint32_t dst, const void* src) {
    asm volatile("cp.async.cg.shared.global [%0], [%1], 16;" :: "r"(dst), "l"(src));
}

// ---------------- kernel 0: zero output ----------------
__global__ void k0_zero(float* __restrict__ out, int n) {
    int i = blockIdx.x * blockDim.x + threadIdx.x;
    if (i < n) out[i] = 0.0f;
}

// ---------------- kernel 1a: per-row max, 1/sum(exp) ----------------
__global__ __launch_bounds__(256) void k1a_stats(const float* __restrict__ probs) {
    const int k = blockIdx.x, b = blockIdx.y, tid = threadIdx.x;
    const float* row = probs + ((size_t)(b * K_ + k)) * S_;
    __shared__ float red[256];

    float m = -1e30f;
    for (int i = tid; i < S_; i += 256) m = fmaxf(m, row[i]);
    red[tid] = m;
    __syncthreads();
    for (int off = 128; off > 0; off >>= 1) {
        if (tid < off) red[tid] = fmaxf(red[tid], red[tid + off]);
        __syncthreads();
    }
    m = red[0];
    __syncthreads();

    float s = 0.0f;
    for (int i = tid; i < S_; i += 256) s += __expf(row[i] - m);
    red[tid] = s;
    __syncthreads();
    for (int off = 128; off > 0; off >>= 1) {
        if (tid < off) red[tid] += red[tid + off];
        __syncthreads();
    }
    if (tid == 0) g_stats[b * KP + k] = make_float2(m, 1.0f / red[0]);
}

// ---------------- kernel 1b: normalized attn [b][kp][s] ----------------
__global__ __launch_bounds__(256) void k1b_attn(const float* __restrict__ probs) {
    const int b = blockIdx.y;
    const int s = blockIdx.x * 256 + threadIdx.x;

    __shared__ float sm[K_], si[K_];
    if (threadIdx.x < K_) {
        float2 st = g_stats[b * KP + threadIdx.x];
        sm[threadIdx.x] = st.x;
        si[threadIdx.x] = st.y;
    }
    __syncthreads();

    float* dst = g_attn + (size_t)b * KP * S_;
#pragma unroll
    for (int k = 0; k < K_; k++) {
        float x = probs[((size_t)(b * K_ + k)) * S_ + s];
        dst[(size_t)k * S_ + s] = __expf(x - sm[k]) * si[k];
    }
    dst[(size_t)29 * S_ + s] = 0.0f;
    dst[(size_t)30 * S_ + s] = 0.0f;
    dst[(size_t)31 * S_ + s] = 0.0f;
}

// ---------------- kernel 2: tiled GEMM, cp.async double buffer ----------------
// grid (SPLIT, C_/128, B_), block 256 = 8 warps.
// warp: kcol = w>>2 (k base 16*kcol), crow = w&3 (c base 32*crow)
// lane: cg = l>>2 (c0 = crow*32 + cg*4), km = l&3 (k set {km,km+4,km+8,km+12}+16*kcol)
__global__ __launch_bounds__(256) void k2_gemm(const float* __restrict__ feats,
                                               float* __restrict__ out) {
    extern __shared__ float sh[];
    float* shF = sh;               // [2][128][FSTRIDE]
    float* shA = sh + 2 * FBUF;    // [2][KP][FSTRIDE]

    const int tid  = threadIdx.x;
    const int b    = blockIdx.z;
    const int cblk = blockIdx.y;
    const int s0   = blockIdx.x * CHUNK;

    const int warp = tid >> 5, lane = tid & 31;
    const int kcol = warp >> 2, crow = warp & 3;
    const int cg = lane >> 2, km = lane & 3;
    const int lc0 = crow * 32 + cg * 4;        // local c base (0..124)
    const int k0  = kcol * 16 + km;            // k = k0 + 4j

    const float* fbase = feats + ((size_t)(b * C_ + cblk * 128)) * S_ + s0;
    const float* abase = g_attn + ((size_t)b * KP) * S_ + s0;

    // staging addresses for this thread
    const int fc = tid >> 3, fch = tid & 7;    // plus +32c per i
    const uint32_t shF_u = s2u(shF);
    const uint32_t shA_u = s2u(shA);

    unsigned long long acc[4][4];
#pragma unroll
    for (int i = 0; i < 4; i++)
#pragma unroll
        for (int j = 0; j < 4; j++) acc[i][j] = 0ull;

    // ---- stage tile 0 ----
    {
        const int buf = 0;
#pragma unroll
        for (int i = 0; i < 4; i++) {
            int c = fc + i * 32;
            cp16(shF_u + (buf * FBUF + c * FSTRIDE + fch * 4) * 4,
                 fbase + (size_t)c * S_ + fch * 4);
        }
        int ak = tid >> 3, ach = tid & 7;
        if (tid < 256) {  // 256 chunks exactly
            cp16(shA_u + (buf * ABUF + ak * FSTRIDE + ach * 4) * 4,
                 abase + (size_t)ak * S_ + ach * 4);
        }
        asm volatile("cp.async.commit_group;");
    }

    for (int t = 0; t < NT; t++) {
        const int buf = t & 1;
        if (t + 1 < NT) {
            const int nbuf = buf ^ 1;
            const int soff = (t + 1) * STILE;
#pragma unroll
            for (int i = 0; i < 4; i++) {
                int c = fc + i * 32;
                cp16(shF_u + (nbuf * FBUF + c * FSTRIDE + fch * 4) * 4,
                     fbase + (size_t)c * S_ + soff + fch * 4);
            }
            int ak = tid >> 3, ach = tid & 7;
            cp16(shA_u + (nbuf * ABUF + ak * FSTRIDE + ach * 4) * 4,
                 abase + (size_t)ak * S_ + soff + ach * 4);
            asm volatile("cp.async.commit_group;");
            asm volatile("cp.async.wait_group 1;");
        } else {
            asm volatile("cp.async.wait_group 0;");
        }
        __syncthreads();

        const float* Fb = shF + buf * FBUF;
        const float* Ab = shA + buf * ABUF;
#pragma unroll 2
        for (int s = 0; s < STILE; s += 4) {
            ulonglong2 ff[4], aa[4];
#pragma unroll
            for (int i = 0; i < 4; i++)
                ff[i] = *(const ulonglong2*)(Fb + (lc0 + i) * FSTRIDE + s);
#pragma unroll
            for (int j = 0; j < 4; j++)
                aa[j] = *(const ulonglong2*)(Ab + (k0 + 4 * j) * FSTRIDE + s);
#pragma unroll
            for (int i = 0; i < 4; i++)
#pragma unroll
                for (int j = 0; j < 4; j++) {
                    fma2(acc[i][j], aa[j].x, ff[i].x);
                    fma2(acc[i][j], aa[j].y, ff[i].y);
                }
        }
        __syncthreads();
    }

    // epilogue: out (B, C, K)
#pragma unroll
    for (int i = 0; i < 4; i++) {
        const int c = cblk * 128 + lc0 + i;
        float* o = out + ((size_t)(b * C_ + c)) * K_;
#pragma unroll
        for (int j = 0; j < 4; j++) {
            const int k = k0 + 4 * j;
            if (k < K_) {
                float lo, hi;
                unpack2(acc[i][j], lo, hi);
                atomicAdd(o + k, lo + hi);
            }
        }
    }
}

extern "C" void kernel_launch(void* const* d_in, const int* in_sizes, int n_in,
                              void* d_out, int out_size) {
    const float* feats = (const float*)d_in[0];  // (16, 512, 128, 128)
    const float* probs = (const float*)d_in[1];  // (16, 29, 128, 128)
    float* out = (float*)d_out;                  // (16, 512, 29, 1)

    k0_zero<<<(out_size + 1023) / 1024, 1024>>>(out, out_size);
    k1a_stats<<<dim3(K_, B_), 256>>>(probs);
    k1b_attn<<<dim3(S_ / 256, B_), 256>>>(probs);

    size_t smem = (size_t)(2 * FBUF + 2 * ABUF) * sizeof(float);  // 46080 B
    k2_gemm<<<dim3(SPLIT, C_ / 128, B_), 256, smem>>>(feats, out);
}

// round 5
// speedup vs baseline: 4.1167x; 2.0533x over previous
#include <cuda_runtime.h>
#include <cstdint>

#define B_  16
#define K_  29
#define KP  32
#define C_  512
#define S_  16384
#define SPLIT 16
#define KS (S_ / SPLIT)        // 1024 s per CTA
#define STILE 32               // s per stage
#define NT (KS / STILE)        // 32 tiles
#define STRIDE 36              // smem row pitch in floats (conflict-free: 36 mod 32 = 4)
#define A_FLOATS (128 * STRIDE)              // 4608
#define B_FLOATS (KP * STRIDE)               // 1152
#define STAGE_FLOATS (A_FLOATS + B_FLOATS)   // 5760
#define SMEM_BYTES (2 * STAGE_FLOATS * 4)    // 46080 <= 48K

// Normalized attention, padded: [B][KP][S] (32 MB). Rows 29..31 zero.
__device__ float g_attn[(size_t)B_ * KP * S_];
__device__ float2 g_stats[B_ * KP];

// ---------------- helpers ----------------
__device__ __forceinline__ uint32_t s2u(const void* p) {
    return (uint32_t)__cvta_generic_to_shared(p);
}
__device__ __forceinline__ void cp16(uint32_t dst, const void* src) {
    asm volatile("cp.async.cg.shared.global [%0], [%1], 16;" :: "r"(dst), "l"(src));
}
__device__ __forceinline__ uint32_t totf32(float f) {
    uint32_t r;
    asm("cvt.rna.tf32.f32 %0, %1;" : "=r"(r) : "f"(f));
    return r;
}
__device__ __forceinline__ void mma_tf32(float* d, const uint32_t* a,
                                         const uint32_t* b) {
    asm volatile(
        "mma.sync.aligned.m16n8k8.row.col.f32.tf32.tf32.f32 "
        "{%0,%1,%2,%3}, {%4,%5,%6,%7}, {%8,%9}, {%0,%1,%2,%3};"
        : "+f"(d[0]), "+f"(d[1]), "+f"(d[2]), "+f"(d[3])
        : "r"(a[0]), "r"(a[1]), "r"(a[2]), "r"(a[3]), "r"(b[0]), "r"(b[1]));
}

// ---------------- kernel 0: zero output ----------------
__global__ void k0_zero(float* __restrict__ out, int n) {
    int i = blockIdx.x * blockDim.x + threadIdx.x;
    if (i < n) out[i] = 0.0f;
}

// ---------------- kernel 1a: per-row max, 1/sum(exp) ----------------
__global__ __launch_bounds__(256) void k1a_stats(const float* __restrict__ probs) {
    const int k = blockIdx.x, b = blockIdx.y, tid = threadIdx.x;
    const float* row = probs + ((size_t)(b * K_ + k)) * S_;
    __shared__ float red[256];

    float m = -1e30f;
    for (int i = tid; i < S_; i += 256) m = fmaxf(m, row[i]);
    red[tid] = m;
    __syncthreads();
    for (int off = 128; off > 0; off >>= 1) {
        if (tid < off) red[tid] = fmaxf(red[tid], red[tid + off]);
        __syncthreads();
    }
    m = red[0];
    __syncthreads();

    float s = 0.0f;
    for (int i = tid; i < S_; i += 256) s += __expf(row[i] - m);
    red[tid] = s;
    __syncthreads();
    for (int off = 128; off > 0; off >>= 1) {
        if (tid < off) red[tid] += red[tid + off];
        __syncthreads();
    }
    if (tid == 0) g_stats[b * KP + k] = make_float2(m, 1.0f / red[0]);
}

// ---------------- kernel 1b: normalized attn [b][kp][s], pad rows zero ----------------
__global__ __launch_bounds__(256) void k1b_attn(const float* __restrict__ probs) {
    const int b = blockIdx.y;
    const int s = blockIdx.x * 256 + threadIdx.x;

    __shared__ float sm[K_], si[K_];
    if (threadIdx.x < K_) {
        float2 st = g_stats[b * KP + threadIdx.x];
        sm[threadIdx.x] = st.x;
        si[threadIdx.x] = st.y;
    }
    __syncthreads();

    float* dst = g_attn + (size_t)b * KP * S_;
#pragma unroll
    for (int k = 0; k < K_; k++) {
        float x = probs[((size_t)(b * K_ + k)) * S_ + s];
        dst[(size_t)k * S_ + s] = __expf(x - sm[k]) * si[k];
    }
    dst[(size_t)29 * S_ + s] = 0.0f;
    dst[(size_t)30 * S_ + s] = 0.0f;
    dst[(size_t)31 * S_ + s] = 0.0f;
}

// ---------------- kernel 2: mma.sync tf32 GEMM ----------------
// grid (SPLIT, C_/128, B_), block 256 = 8 warps.
// Warp w: c rows [16w, 16w+16), all 32 k via 4 n-tiles of m16n8k8.
__global__ __launch_bounds__(256) void k2_mma(const float* __restrict__ feats,
                                              float* __restrict__ out) {
    extern __shared__ float sh[];
    float* shA0 = sh;                    // [2][128][STRIDE]
    float* shB0 = sh + 2 * A_FLOATS;     // [2][KP][STRIDE]

    const int tid  = threadIdx.x;
    const int warp = tid >> 5, lane = tid & 31;
    const int b    = blockIdx.z;
    const int cblk = blockIdx.y;
    const int s0   = blockIdx.x * KS;

    const int r = lane >> 2;      // fragment row within 8
    const int q = lane & 3;       // fragment col within 4
    const int c0 = warp * 16;     // warp's local c base

    const float* fbase = feats + ((size_t)(b * C_ + cblk * 128)) * S_ + s0;
    const float* abase = g_attn + ((size_t)b * KP) * S_ + s0;

    const uint32_t shA_u = s2u(shA0);
    const uint32_t shB_u = s2u(shB0);
    const int frow = tid >> 3, fcol = tid & 7;   // staging coords

    float acc[4][4];
#pragma unroll
    for (int n = 0; n < 4; n++)
#pragma unroll
        for (int i = 0; i < 4; i++) acc[n][i] = 0.0f;

    // ---- stage tile 0 ----
#pragma unroll
    for (int i = 0; i < 4; i++) {
        int row = frow + i * 32;
        cp16(shA_u + (row * STRIDE + fcol * 4) * 4,
             fbase + (size_t)row * S_ + fcol * 4);
    }
    cp16(shB_u + (frow * STRIDE + fcol * 4) * 4,
         abase + (size_t)frow * S_ + fcol * 4);
    asm volatile("cp.async.commit_group;");

    for (int t = 0; t < NT; t++) {
        const int buf = t & 1;
        if (t + 1 < NT) {
            const int nbuf = buf ^ 1;
            const int soff = (t + 1) * STILE;
#pragma unroll
            for (int i = 0; i < 4; i++) {
                int row = frow + i * 32;
                cp16(shA_u + (nbuf * A_FLOATS + row * STRIDE + fcol * 4) * 4,
                     fbase + (size_t)row * S_ + soff + fcol * 4);
            }
            cp16(shB_u + (nbuf * B_FLOATS + frow * STRIDE + fcol * 4) * 4,
                 abase + (size_t)frow * S_ + soff + fcol * 4);
            asm volatile("cp.async.commit_group;");
            asm volatile("cp.async.wait_group 1;");
        } else {
            asm volatile("cp.async.wait_group 0;");
        }
        __syncthreads();

        const float* A = shA0 + buf * A_FLOATS;
        const float* Bm = shB0 + buf * B_FLOATS;

#pragma unroll
        for (int ks = 0; ks < STILE / 8; ks++) {
            const int so = ks * 8;
            uint32_t a[4];
            a[0] = totf32(A[(c0 + r) * STRIDE + so + q]);
            a[1] = totf32(A[(c0 + r + 8) * STRIDE + so + q]);
            a[2] = totf32(A[(c0 + r) * STRIDE + so + q + 4]);
            a[3] = totf32(A[(c0 + r + 8) * STRIDE + so + q + 4]);
#pragma unroll
            for (int n = 0; n < 4; n++) {
                uint32_t bb[2];
                bb[0] = totf32(Bm[(n * 8 + r) * STRIDE + so + q]);
                bb[1] = totf32(Bm[(n * 8 + r) * STRIDE + so + q + 4]);
                mma_tf32(acc[n], a, bb);
            }
        }
        __syncthreads();
    }

    // ---- epilogue: D fragment -> out (B, C, K) via atomicAdd ----
    const int cg = cblk * 128 + c0 + r;
#pragma unroll
    for (int n = 0; n < 4; n++) {
#pragma unroll
        for (int i = 0; i < 4; i++) {
            const int c = cg + (i >> 1) * 8;            // d0,d1 -> row r; d2,d3 -> r+8
            const int k = n * 8 + q * 2 + (i & 1);
            if (k < K_) {
                float* o = out + ((size_t)(b * C_ + c)) * K_ + k;
                atomicAdd(o, acc[n][i]);
            }
        }
    }
}

extern "C" void kernel_launch(void* const* d_in, const int* in_sizes, int n_in,
                              void* d_out, int out_size) {
    const float* feats = (const float*)d_in[0];  // (16, 512, 128, 128)
    const float* probs = (const float*)d_in[1];  // (16, 29, 128, 128)
    float* out = (float*)d_out;                  // (16, 512, 29, 1)

    k0_zero<<<(out_size + 1023) / 1024, 1024>>>(out, out_size);
    k1a_stats<<<dim3(K_, B_), 256>>>(probs);
    k1b_attn<<<dim3(S_ / 256, B_), 256>>>(probs);
    k2_mma<<<dim3(SPLIT, C_ / 128, B_), 256, SMEM_BYTES>>>(feats, out);
}

// round 6
// speedup vs baseline: 4.2967x; 1.0437x over previous
#include <cuda_runtime.h>
#include <cstdint>

#define B_  16
#define K_  29
#define KP  32
#define C_  512
#define S_  16384
#define SPLIT 32
#define KS (S_ / SPLIT)        // 512 s per CTA
#define STILE 32               // s per stage
#define NT (KS / STILE)        // 16 stages of work
#define NSTAGE 4               // ring depth
#define STRIDE 36              // smem row pitch (floats), conflict-free
#define A_FLOATS (128 * STRIDE)              // 4608
#define B_FLOATS (KP * STRIDE)               // 1152
#define STAGE_FLOATS (A_FLOATS + B_FLOATS)   // 5760
#define SMEM_BYTES (NSTAGE * STAGE_FLOATS * 4)  // 92160

#define OUTN (B_ * C_ * K_)    // 237568

// Per (b,k): {row max, 1/sum}
__device__ float2 g_stats[B_ * KP];

// ---------------- helpers ----------------
__device__ __forceinline__ uint32_t s2u(const void* p) {
    return (uint32_t)__cvta_generic_to_shared(p);
}
__device__ __forceinline__ void cp16(uint32_t dst, const void* src) {
    asm volatile("cp.async.cg.shared.global [%0], [%1], 16;" :: "r"(dst), "l"(src));
}
__device__ __forceinline__ uint32_t totf32(float f) {
    uint32_t r;
    asm("cvt.rna.tf32.f32 %0, %1;" : "=r"(r) : "f"(f));
    return r;
}
__device__ __forceinline__ void mma_tf32(float* d, const uint32_t* a,
                                         const uint32_t* b) {
    asm volatile(
        "mma.sync.aligned.m16n8k8.row.col.f32.tf32.tf32.f32 "
        "{%0,%1,%2,%3}, {%4,%5,%6,%7}, {%8,%9}, {%0,%1,%2,%3};"
        : "+f"(d[0]), "+f"(d[1]), "+f"(d[2]), "+f"(d[3])
        : "r"(a[0]), "r"(a[1]), "r"(a[2]), "r"(a[3]), "r"(b[0]), "r"(b[1]));
}

// ---------------- kernel 1: zero out + per-(b,k) max & 1/sum(exp) ----------------
__global__ __launch_bounds__(256) void k1_stats(const float* __restrict__ probs,
                                                float* __restrict__ out) {
    const int k = blockIdx.x, b = blockIdx.y, tid = threadIdx.x;
    // zero the output (grid covers OUTN in 2 strides)
    const int gsz = gridDim.x * gridDim.y * 256;
    for (int i = (blockIdx.y * gridDim.x + blockIdx.x) * 256 + tid; i < OUTN; i += gsz)
        out[i] = 0.0f;

    const float* row = probs + ((size_t)(b * K_ + k)) * S_;
    __shared__ float red[256];

    float m = -1e30f;
    for (int i = tid; i < S_; i += 256) m = fmaxf(m, row[i]);
    red[tid] = m;
    __syncthreads();
    for (int off = 128; off > 0; off >>= 1) {
        if (tid < off) red[tid] = fmaxf(red[tid], red[tid + off]);
        __syncthreads();
    }
    m = red[0];
    __syncthreads();

    float s = 0.0f;
    for (int i = tid; i < S_; i += 256) s += __expf(row[i] - m);
    red[tid] = s;
    __syncthreads();
    for (int off = 128; off > 0; off >>= 1) {
        if (tid < off) red[tid] += red[tid + off];
        __syncthreads();
    }
    if (tid == 0) g_stats[b * KP + k] = make_float2(m, 1.0f / red[0]);
}

// ---------------- kernel 2: fused softmax + mma.sync tf32 GEMM ----------------
// grid (SPLIT, C_/128, B_), block 256 = 8 warps.
// B tile staged as RAW probs, exp-normalized in place (each thread exps the
// exact values it cp.async'd, so only its own wait_group is needed before).
__global__ __launch_bounds__(256) void k2_mma(const float* __restrict__ feats,
                                              const float* __restrict__ probs,
                                              float* __restrict__ out) {
    extern __shared__ float sh[];

    const int tid  = threadIdx.x;
    const int warp = tid >> 5, lane = tid & 31;
    const int b    = blockIdx.z;
    const int cblk = blockIdx.y;
    const int s0   = blockIdx.x * KS;

    const int r = lane >> 2;      // fragment row within 8
    const int q = lane & 3;       // fragment col within 4
    const int c0 = warp * 16;     // warp's local c base

    const int frow = tid >> 3;    // staging row (A: +32i; B: k row)
    const int fcol = tid & 7;     // 16 B column

    const int kclamp = frow < K_ ? frow : (K_ - 1);
    const float2 st = g_stats[b * KP + kclamp];
    const float km = st.x, kinv = st.y;

    const float* fbase = feats + ((size_t)(b * C_ + cblk * 128)) * S_ + s0;
    const float* pbase = probs + ((size_t)(b * K_ + kclamp)) * S_ + s0;

    const uint32_t sh_u = s2u(sh);

    float acc[4][4];
#pragma unroll
    for (int n = 0; n < 4; n++)
#pragma unroll
        for (int i = 0; i < 4; i++) acc[n][i] = 0.0f;

    // ---- prologue: fill stages 0..NSTAGE-2 ----
#pragma unroll
    for (int p = 0; p < NSTAGE - 1; p++) {
        const uint32_t sbuf = sh_u + p * STAGE_FLOATS * 4;
        const int soff = p * STILE;
#pragma unroll
        for (int i = 0; i < 4; i++) {
            int row = frow + i * 32;
            cp16(sbuf + (row * STRIDE + fcol * 4) * 4,
                 fbase + (size_t)row * S_ + soff + fcol * 4);
        }
        cp16(sbuf + (A_FLOATS + frow * STRIDE + fcol * 4) * 4,
             pbase + soff + fcol * 4);
        asm volatile("cp.async.commit_group;");
    }

    for (int t = 0; t < NT; t++) {
        const int slot = t & (NSTAGE - 1);
        // issue loads for stage t+NSTAGE-1 (slot was last read in iter t-1)
        const int tn = t + NSTAGE - 1;
        if (tn < NT) {
            const uint32_t sbuf = sh_u + (tn & (NSTAGE - 1)) * STAGE_FLOATS * 4;
            const int soff = tn * STILE;
#pragma unroll
            for (int i = 0; i < 4; i++) {
                int row = frow + i * 32;
                cp16(sbuf + (row * STRIDE + fcol * 4) * 4,
                     fbase + (size_t)row * S_ + soff + fcol * 4);
            }
            cp16(sbuf + (A_FLOATS + frow * STRIDE + fcol * 4) * 4,
                 pbase + soff + fcol * 4);
        }
        asm volatile("cp.async.commit_group;");
        asm volatile("cp.async.wait_group %0;" :: "n"(NSTAGE - 1));

        // in-place softmax on this thread's own staged B values
        float* Bb = sh + slot * STAGE_FLOATS + A_FLOATS;
        {
            float4* bp = (float4*)(Bb + frow * STRIDE + fcol * 4);
            float4 v = *bp;
            v.x = __expf(v.x - km) * kinv;
            v.y = __expf(v.y - km) * kinv;
            v.z = __expf(v.z - km) * kinv;
            v.w = __expf(v.w - km) * kinv;
            *bp = v;
        }
        __syncthreads();   // A arrival + exp results visible to all

        const float* A = sh + slot * STAGE_FLOATS;
#pragma unroll
        for (int ks = 0; ks < STILE / 8; ks++) {
            const int so = ks * 8;
            uint32_t a[4];
            a[0] = totf32(A[(c0 + r) * STRIDE + so + q]);
            a[1] = totf32(A[(c0 + r + 8) * STRIDE + so + q]);
            a[2] = totf32(A[(c0 + r) * STRIDE + so + q + 4]);
            a[3] = totf32(A[(c0 + r + 8) * STRIDE + so + q + 4]);
#pragma unroll
            for (int n = 0; n < 4; n++) {
                uint32_t bb[2];
                bb[0] = totf32(Bb[(n * 8 + r) * STRIDE + so + q]);
                bb[1] = totf32(Bb[(n * 8 + r) * STRIDE + so + q + 4]);
                mma_tf32(acc[n], a, bb);
            }
        }
        __syncthreads();   // all reads of this slot done before it is refilled
    }

    // ---- epilogue: D fragment -> out (B, C, K) via atomicAdd ----
    const int cg = cblk * 128 + c0 + r;
#pragma unroll
    for (int n = 0; n < 4; n++) {
#pragma unroll
        for (int i = 0; i < 4; i++) {
            const int c = cg + (i >> 1) * 8;
            const int k = n * 8 + q * 2 + (i & 1);
            if (k < K_) {
                float* o = out + ((size_t)(b * C_ + c)) * K_ + k;
                atomicAdd(o, acc[n][i]);
            }
        }
    }
}

extern "C" void kernel_launch(void* const* d_in, const int* in_sizes, int n_in,
                              void* d_out, int out_size) {
    const float* feats = (const float*)d_in[0];  // (16, 512, 128, 128)
    const float* probs = (const float*)d_in[1];  // (16, 29, 128, 128)
    float* out = (float*)d_out;                  // (16, 512, 29, 1)

    cudaFuncSetAttribute(k2_mma, cudaFuncAttributeMaxDynamicSharedMemorySize,
                         SMEM_BYTES);
    cudaFuncSetAttribute(k2_mma, cudaFuncAttributePreferredSharedMemoryCarveout,
                         cudaSharedmemCarveoutMaxShared);

    k1_stats<<<dim3(K_, B_), 256>>>(probs, out);
    k2_mma<<<dim3(SPLIT, C_ / 128, B_), 256, SMEM_BYTES>>>(feats, probs, out);
}